// round 2
// baseline (speedup 1.0000x reference)
#include <cuda_runtime.h>
#include <cuda_bf16.h>

// Problem constants
#define BB 2
#define SS 1024
#define HID 4096
#define HH 32
#define QL 1536
#define KVL 512
#define ROPE 64
#define VV 128
#define DD 576              // KVL + ROPE
#define MM (BB*SS)          // 2048

// ---------------- scratch (device globals; no allocs allowed) ----------------
__device__ __align__(16) float g_bufA[(size_t)MM * 2048];              // qa_raw then qpe_raw
__device__ __align__(16) float g_qa[(size_t)MM * QL];                  // rmsnormed q_a
__device__ __align__(16) float g_ckv[(size_t)MM * DD];                 // hidden @ w_kv_a
__device__ __align__(16) float g_keys[(size_t)MM * DD];                // [kva | rope(k_pe)]
__device__ __align__(16) float g_query[(size_t)BB*HH*SS*DD];           // [q_abs | rope(q_pe)]
__device__ __align__(16) float g_scores[(size_t)BB*HH*SS*SS];          // attn scores/probs
__device__ __align__(16) float g_ctx[(size_t)BB*HH*SS*KVL];            // attn @ kva
__device__ __align__(16) float g_attout[(size_t)MM * HID];             // [B,S,H*V]

// ---------------- generic strided-batched SGEMM: C = A @ B (or A @ B^T) ------
// 128x128 tile, BK=8, 256 threads, 8x8 per thread.
// Requires M % 128 == 0 and K % 8 == 0 (true for all call sites).
// N is guarded (576, 128 cases).
template<bool TRANSB>
__global__ __launch_bounds__(256, 2)
void gemm_kernel(const float* __restrict__ A, const float* __restrict__ Bm,
                 float* __restrict__ C,
                 int M, int N, int K, int lda, int ldb, int ldc,
                 long long sAo, long long sAi, long long sBo, long long sBi,
                 long long sCo, long long sCi, int innerCnt)
{
    int z = blockIdx.z;
    int outer = z / innerCnt;
    int inner = z - outer * innerCnt;
    A  += outer * sAo + inner * sAi;
    Bm += outer * sBo + inner * sBi;
    C  += outer * sCo + inner * sCi;

    __shared__ float As[8][128];
    __shared__ float Bs[8][128];

    int tid = threadIdx.x;
    int bm = blockIdx.y * 128;
    int bn = blockIdx.x * 128;

    // A tile load: 128 rows x 8 cols, one float4 per thread, stored transposed
    int aRow = tid >> 1;
    int aCol = (tid & 1) << 2;
    // B tile load indices
    int bRow, bCol;
    if (TRANSB) { bRow = tid >> 1; bCol = (tid & 1) << 2; }   // 128 N-rows x 8 k-cols
    else        { bRow = tid >> 5; bCol = (tid & 31) << 2; }  // 8 k-rows x 128 N-cols

    int ty = tid >> 4, tx = tid & 15;
    float acc[8][8] = {};

    for (int k0 = 0; k0 < K; k0 += 8) {
        float4 av = *reinterpret_cast<const float4*>(
            A + (long long)(bm + aRow) * lda + k0 + aCol);
        As[aCol + 0][aRow] = av.x; As[aCol + 1][aRow] = av.y;
        As[aCol + 2][aRow] = av.z; As[aCol + 3][aRow] = av.w;

        if (TRANSB) {
            float4 bv = make_float4(0.f, 0.f, 0.f, 0.f);
            if (bn + bRow < N)
                bv = *reinterpret_cast<const float4*>(
                    Bm + (long long)(bn + bRow) * ldb + k0 + bCol);
            Bs[bCol + 0][bRow] = bv.x; Bs[bCol + 1][bRow] = bv.y;
            Bs[bCol + 2][bRow] = bv.z; Bs[bCol + 3][bRow] = bv.w;
        } else {
            float4 bv = make_float4(0.f, 0.f, 0.f, 0.f);
            if (bn + bCol < N)
                bv = *reinterpret_cast<const float4*>(
                    Bm + (long long)(k0 + bRow) * ldb + bn + bCol);
            *reinterpret_cast<float4*>(&Bs[bRow][bCol]) = bv;
        }
        __syncthreads();

        #pragma unroll
        for (int k = 0; k < 8; k++) {
            float ra[8], rb[8];
            #pragma unroll
            for (int i = 0; i < 8; i++) ra[i] = As[k][ty * 8 + i];
            #pragma unroll
            for (int j = 0; j < 8; j++) rb[j] = Bs[k][tx * 8 + j];
            #pragma unroll
            for (int i = 0; i < 8; i++)
                #pragma unroll
                for (int j = 0; j < 8; j++)
                    acc[i][j] = fmaf(ra[i], rb[j], acc[i][j]);
        }
        __syncthreads();
    }

    #pragma unroll
    for (int i = 0; i < 8; i++) {
        int row = bm + ty * 8 + i;
        #pragma unroll
        for (int j = 0; j < 8; j += 4) {
            int col = bn + tx * 8 + j;
            if (col < N)
                *reinterpret_cast<float4*>(C + (long long)row * ldc + col) =
                    make_float4(acc[i][j], acc[i][j+1], acc[i][j+2], acc[i][j+3]);
        }
    }
}

// ---------------- RMSNorm: one block per row ----------------
__global__ void rmsnorm_kernel(const float* __restrict__ in, const float* __restrict__ w,
                               float* __restrict__ out, int cols, int ldin, int ldout)
{
    long long row = blockIdx.x;
    const float* x = in + row * ldin;
    float* y = out + row * ldout;
    int tid = threadIdx.x;
    float ss = 0.f;
    for (int c = tid; c < cols; c += 256) { float v = x[c]; ss += v * v; }
    __shared__ float red[256];
    red[tid] = ss; __syncthreads();
    for (int s = 128; s > 0; s >>= 1) {
        if (tid < s) red[tid] += red[tid + s];
        __syncthreads();
    }
    float r = rsqrtf(red[0] / (float)cols + 1e-6f);
    for (int c = tid; c < cols; c += 256) y[c] = x[c] * r * w[c];
}

// ---------------- RoPE (interleaved deinterleave + rotate-half) ----------------
// out[j]    = x[2j]*cos(f_j) - x[2j+1]*sin(f_j)     (j in [0,32))
// out[j+32] = x[2j+1]*cos(f_j) + x[2j]*sin(f_j),  f_j = pos * 10000^{-j/32}
__device__ __forceinline__ void rope_pair(float x0, float x1, float pos, int j,
                                          float& o0, float& o1)
{
    float inv = expf(-(float)j * 0.28782313662425581f);  // ln(10000)/32
    float f = pos * inv;
    float c = cosf(f), s = sinf(f);
    o0 = x0 * c - x1 * s;
    o1 = x1 * c + x0 * s;
}

__global__ void rope_k_kernel(const float* __restrict__ ckv, const int* __restrict__ pos_ids,
                              float* __restrict__ keys)
{
    int gid = blockIdx.x * blockDim.x + threadIdx.x;  // row*32 + j
    if (gid >= MM * 32) return;
    int j = gid & 31;
    int row = gid >> 5;
    float pos = (float)pos_ids[row];
    float x0 = ckv[(long long)row * DD + KVL + 2 * j];
    float x1 = ckv[(long long)row * DD + KVL + 2 * j + 1];
    float o0, o1;
    rope_pair(x0, x1, pos, j, o0, o1);
    keys[(long long)row * DD + KVL + j] = o0;
    keys[(long long)row * DD + KVL + 32 + j] = o1;
}

__global__ void rope_q_kernel(const float* __restrict__ qpe, const int* __restrict__ pos_ids,
                              float* __restrict__ query)
{
    int gid = blockIdx.x * blockDim.x + threadIdx.x;  // ((b*S+s)*H + h)*32 + j
    if (gid >= MM * HH * 32) return;
    int j = gid & 31;
    int h = (gid >> 5) & (HH - 1);
    int row = gid >> 10;                  // b*S + s
    int b = row >> 10;                    // S = 1024
    int s = row & (SS - 1);
    float pos = (float)pos_ids[row];
    float x0 = qpe[(long long)row * (HH * ROPE) + h * ROPE + 2 * j];
    float x1 = qpe[(long long)row * (HH * ROPE) + h * ROPE + 2 * j + 1];
    float o0, o1;
    rope_pair(x0, x1, pos, j, o0, o1);
    long long ob = (((long long)(b * HH + h)) * SS + s) * DD + KVL;
    query[ob + j] = o0;
    query[ob + 32 + j] = o1;
}

// ---------------- causal softmax (in place on scores) ----------------
__global__ void softmax_kernel(float* __restrict__ sc)
{
    int i = blockIdx.x;   // query position
    int z = blockIdx.y;   // b*H + h
    long long base = ((long long)z * SS + i) * SS;
    int tid = threadIdx.x;
    const float scale = 0.07216878364870322f;  // 1/sqrt(192)

    float lm = -1e30f;
    for (int j = tid; j <= i; j += 256) lm = fmaxf(lm, sc[base + j]);
    __shared__ float red[256];
    red[tid] = lm; __syncthreads();
    for (int s = 128; s > 0; s >>= 1) {
        if (tid < s) red[tid] = fmaxf(red[tid], red[tid + s]);
        __syncthreads();
    }
    float m = red[0] * scale;
    __syncthreads();

    float ls = 0.f;
    for (int j = tid; j <= i; j += 256) {
        float e = expf(sc[base + j] * scale - m);
        sc[base + j] = e;
        ls += e;
    }
    red[tid] = ls; __syncthreads();
    for (int s = 128; s > 0; s >>= 1) {
        if (tid < s) red[tid] += red[tid + s];
        __syncthreads();
    }
    float inv = 1.f / red[0];
    for (int j = tid; j <= i; j += 256) sc[base + j] *= inv;
    for (int j = i + 1 + tid; j < SS; j += 256) sc[base + j] = 0.f;
}

// ---------------- launch ----------------
extern "C" void kernel_launch(void* const* d_in, const int* in_sizes, int n_in,
                              void* d_out, int out_size)
{
    const float* hidden    = (const float*)d_in[0];
    // d_in[1] attention_mask: causal -1e9 mask — equivalent to hard j<=i mask, unused
    const int*   pos       = (const int*)d_in[2];
    const float* w_q_a     = (const float*)d_in[3];
    const float* q_a_ln_w  = (const float*)d_in[4];
    const float* q_rope    = (const float*)d_in[5];
    const float* fusedqk   = (const float*)d_in[6];
    const float* w_kv_a    = (const float*)d_in[7];
    const float* kv_a_ln_w = (const float*)d_in[8];
    const float* v_up      = (const float*)d_in[9];
    const float* w_o       = (const float*)d_in[10];
    float* out = (float*)d_out;

    float *bufA, *qa, *ckv, *keys, *query, *scores, *ctx, *attout;
    cudaGetSymbolAddress((void**)&bufA,   g_bufA);
    cudaGetSymbolAddress((void**)&qa,     g_qa);
    cudaGetSymbolAddress((void**)&ckv,    g_ckv);
    cudaGetSymbolAddress((void**)&keys,   g_keys);
    cudaGetSymbolAddress((void**)&query,  g_query);
    cudaGetSymbolAddress((void**)&scores, g_scores);
    cudaGetSymbolAddress((void**)&ctx,    g_ctx);
    cudaGetSymbolAddress((void**)&attout, g_attout);

    dim3 blk(256);

    // 1. qa_raw = hidden @ w_q_a  [2048,1536]
    gemm_kernel<false><<<dim3(12, 16, 1), blk>>>(hidden, w_q_a, bufA,
        2048, 1536, 4096, 4096, 1536, 1536, 0, 0, 0, 0, 0, 0, 1);

    // 2. ckv = hidden @ w_kv_a  [2048,576]
    gemm_kernel<false><<<dim3(5, 16, 1), blk>>>(hidden, w_kv_a, ckv,
        2048, 576, 4096, 4096, 576, 576, 0, 0, 0, 0, 0, 0, 1);

    // 3. qa = rmsnorm(qa_raw)
    rmsnorm_kernel<<<2048, 256>>>(bufA, q_a_ln_w, qa, 1536, 1536, 1536);

    // 4. keys[:, :512] = rmsnorm(ckv[:, :512])
    rmsnorm_kernel<<<2048, 256>>>(ckv, kv_a_ln_w, keys, 512, 576, 576);

    // 5. keys[:, 512:576] = rope(ckv[:, 512:576])
    rope_k_kernel<<<(MM * 32) / 256, 256>>>(ckv, pos, keys);

    // 6. qpe_raw = qa @ q_rope  [2048, 2048]
    gemm_kernel<false><<<dim3(16, 16, 1), blk>>>(qa, q_rope, bufA,
        2048, 2048, 1536, 1536, 2048, 2048, 0, 0, 0, 0, 0, 0, 1);

    // 7. query[..., 512:576] = rope(qpe_raw per head)
    rope_q_kernel<<<(MM * HH * 32) / 256, 256>>>(bufA, pos, query);

    // 8. query[..., :512] = qa @ fusedqk[h]  (batched over b,h)
    gemm_kernel<false><<<dim3(4, 8, 64), blk>>>(qa, fusedqk, query,
        1024, 512, 1536, 1536, 512, 576,
        (long long)1024 * 1536, 0,
        0, (long long)1536 * 512,
        (long long)32 * 1024 * 576, (long long)1024 * 576, 32);

    // 9. scores = query @ keys^T  (batched over b,h)
    gemm_kernel<true><<<dim3(8, 8, 64), blk>>>(query, keys, scores,
        1024, 1024, 576, 576, 576, 1024,
        (long long)32 * 1024 * 576, (long long)1024 * 576,
        (long long)1024 * 576, 0,
        (long long)32 * 1024 * 1024, (long long)1024 * 1024, 32);

    // 10. causal softmax in place
    softmax_kernel<<<dim3(1024, 64), 256>>>(scores);

    // 11. ctx = attn @ kva  (kva = keys[:, :512], ldb=576)
    gemm_kernel<false><<<dim3(4, 8, 64), blk>>>(scores, keys, ctx,
        1024, 512, 1024, 1024, 576, 512,
        (long long)32 * 1024 * 1024, (long long)1024 * 1024,
        (long long)1024 * 576, 0,
        (long long)32 * 1024 * 512, (long long)1024 * 512, 32);

    // 12. attout[b, s, h*128:(h+1)*128] = ctx @ v_up[h]
    gemm_kernel<false><<<dim3(1, 8, 64), blk>>>(ctx, v_up, attout,
        1024, 128, 512, 512, 128, 4096,
        (long long)32 * 1024 * 512, (long long)1024 * 512,
        0, (long long)512 * 128,
        (long long)1024 * 4096, 128, 32);

    // 13. out = attout @ w_o
    gemm_kernel<false><<<dim3(32, 16, 1), blk>>>(attout, w_o, out,
        2048, 4096, 4096, 4096, 4096, 4096, 0, 0, 0, 0, 0, 0, 1);
}